// round 2
// baseline (speedup 1.0000x reference)
#include <cuda_runtime.h>
#include <math.h>
#include <stdint.h>

#define Bb 32
#define Tt 512
#define Dd 512
#define Hh 2048
#define H3 6144
#define Pp 1024
#define MT (Bb*Tt)   // 16384

// ---------------- scratch (device globals) ---------------------------------------
__device__ float g_A1[(size_t)MT * 1024];   //  64 MB relu(x@W1^T+b1), rows (b*T+t)
__device__ float g_A2[(size_t)MT * Hh];     // 128 MB relu(.@W2^T+b2), rows (b*T+t)
__device__ float g_GI[(size_t)MT * H3];     // 384 MB gi, layout (T, 3H, B)
__device__ float g_HS[(size_t)Tt * Hh * Bb];// 128 MB h history, layout (T, H, B)
__device__ float g_S [(size_t)MT * Pp];     //  64 MB relu(h@W3^T+b3), rows (t*B+b)
__device__ float g_WT[(size_t)Hh * H3];     //  50 MB W_hh transposed: (K=2048, 3H)
__device__ float g_h0T[Hh * Bb];            // h0 transposed (H, B)

// ---------------- f32x2 helpers ---------------------------------------------------
__device__ __forceinline__ unsigned long long fma2(unsigned long long a,
                                                   unsigned long long b,
                                                   unsigned long long c) {
    unsigned long long d;
    asm("fma.rn.f32x2 %0, %1, %2, %3;" : "=l"(d) : "l"(a), "l"(b), "l"(c));
    return d;
}
__device__ __forceinline__ unsigned long long pack2(float x) {
    unsigned long long d;
    asm("mov.b64 %0, {%1, %1};" : "=l"(d) : "f"(x));
    return d;
}
__device__ __forceinline__ float2 ull2f2(unsigned long long v) {
    float2 f;
    asm("mov.b64 {%0, %1}, %2;" : "=f"(f.x), "=f"(f.y) : "l"(v));
    return f;
}
__device__ __forceinline__ float sigm(float x) { return 1.f / (1.f + expf(-x)); }

// ---------------- generic TN SGEMM -------------------------------------------------
// C = act(A @ B^T + bias). aMode: 0 = A row-major (M,K) rows r;
//                          1 = A stored (T, K, B): A[r][k] = A[(r>>5)*K*32 + k*32 + (r&31)]
// outMode: 0 = C[r][n];  2 = C stored (T, N, B): addr = t*N*32 + n*32 + b, r = b*T + t
#define BM 128
#define BN 128
#define BK 8
#define TM 8
#define TN 8

__global__ __launch_bounds__(256)
void sgemm_tn(const float* __restrict__ A, const float* __restrict__ B,
              const float* __restrict__ bias, float* __restrict__ C,
              int M, int N, int K, int doRelu, int aMode, int outMode)
{
    __shared__ float As[BK][BM];
    __shared__ float Bs[BK][BN];
    const int tid = threadIdx.x;
    const int tx  = tid & 15;
    const int ty  = tid >> 4;
    const int lr  = tid >> 1;
    const int lk  = (tid & 1) * 4;

    const float* Bp = B + (size_t)(blockIdx.x * BN + lr) * K + lk;
    const int rowg = blockIdx.y * BM + lr;
    const float* Ap0 = A + (size_t)rowg * K + lk;                       // aMode 0
    const float* Ap1 = A + (size_t)(rowg >> 5) * K * 32 + (rowg & 31);  // aMode 1

    float acc[TM][TN];
#pragma unroll
    for (int i = 0; i < TM; i++)
#pragma unroll
        for (int j = 0; j < TN; j++) acc[i][j] = 0.f;

    for (int k0 = 0; k0 < K; k0 += BK) {
        if (aMode == 0) {
            float4 av = *(const float4*)(Ap0 + k0);
            As[lk + 0][lr] = av.x; As[lk + 1][lr] = av.y;
            As[lk + 2][lr] = av.z; As[lk + 3][lr] = av.w;
        } else {
#pragma unroll
            for (int q = 0; q < 4; q++)
                As[lk + q][lr] = Ap1[(size_t)(k0 + lk + q) * 32];
        }
        float4 bv = *(const float4*)(Bp + k0);
        Bs[lk + 0][lr] = bv.x; Bs[lk + 1][lr] = bv.y;
        Bs[lk + 2][lr] = bv.z; Bs[lk + 3][lr] = bv.w;
        __syncthreads();
#pragma unroll
        for (int k = 0; k < BK; k++) {
            float ar[TM], br[TN];
#pragma unroll
            for (int i = 0; i < TM; i++) ar[i] = As[k][ty * TM + i];
#pragma unroll
            for (int j = 0; j < TN; j++) br[j] = Bs[k][tx * TN + j];
#pragma unroll
            for (int i = 0; i < TM; i++)
#pragma unroll
                for (int j = 0; j < TN; j++)
                    acc[i][j] = fmaf(ar[i], br[j], acc[i][j]);
        }
        __syncthreads();
    }

#pragma unroll
    for (int i = 0; i < TM; i++) {
        int r = blockIdx.y * BM + ty * TM + i;
        int colb = blockIdx.x * BN + tx * TN;
        if (outMode == 0) {
            float* Cp = C + (size_t)r * N + colb;
#pragma unroll
            for (int j = 0; j < TN; j++) {
                float v = acc[i][j] + bias[colb + j];
                if (doRelu) v = fmaxf(v, 0.f);
                Cp[j] = v;
            }
        } else {  // outMode 2: r = b*T + t  ->  (t, n, b)
            int t = r & (Tt - 1), b = r >> 9;
            float* Cp = C + (size_t)t * N * 32 + b;
#pragma unroll
            for (int j = 0; j < TN; j++) {
                float v = acc[i][j] + bias[colb + j];
                if (doRelu) v = fmaxf(v, 0.f);
                Cp[(size_t)(colb + j) * 32] = v;
            }
        }
    }
}

// ---------------- one-time transposes ---------------------------------------------
__global__ void transpose_whh(const float* __restrict__ Whh, float* __restrict__ WT)
{
    __shared__ float tile[32][33];
    int c0 = blockIdx.x * 32, k0 = blockIdx.y * 32;
    int x = threadIdx.x, y0 = threadIdx.y;           // block 32 x 8
#pragma unroll
    for (int y = y0; y < 32; y += 8)
        tile[y][x] = Whh[(size_t)(c0 + y) * Hh + k0 + x];
    __syncthreads();
#pragma unroll
    for (int y = y0; y < 32; y += 8)
        WT[(size_t)(k0 + y) * H3 + c0 + x] = tile[x][y];
}

__global__ void transpose_h0(const float* __restrict__ h0, float* __restrict__ h0T)
{
    int i = blockIdx.x * 256 + threadIdx.x;          // i over H*B
    if (i < Hh * Bb) {
        int c = i >> 5, b = i & 31;
        h0T[i] = h0[(size_t)b * Hh + c];
    }
}

// ---------------- GRU step: FMA2 register-tiled -----------------------------------
// grid = 128 blocks (16 hcols each), block = 384 threads = 12 warps =
// (gate g in [0,3)) x (ksplit s in [0,4), 512 k each).
// Lane tiling: cg = lane>>2 (8 col-groups, 2 cols each), bg = lane&3 (4 bpair-groups,
// 4 bpairs = 8 batches each). acc[2][4] f32x2.
__global__ __launch_bounds__(384)
void gru_step(const float* __restrict__ gi_t,    // (3H, B) slice for this t
              const float* __restrict__ hprevT,  // (H, B)
              const float* __restrict__ WT,      // (K, 3H)
              const float* __restrict__ bhh,
              float* __restrict__ hnewT)         // (H, B)
{
    __shared__ float2 sred[12][16][16];  // [warp][colLocal][bpair]  24 KB

    const int tid  = threadIdx.x;
    const int w    = tid >> 5;
    const int lane = tid & 31;
    const int gate = w >> 2;
    const int ks   = w & 3;
    const int cg   = lane >> 2;
    const int bg   = lane & 3;
    const int colbase = blockIdx.x * 16;

    unsigned long long acc[2][4];
#pragma unroll
    for (int i = 0; i < 2; i++)
#pragma unroll
        for (int j = 0; j < 4; j++) acc[i][j] = 0ull;

    const float* wp = WT + (size_t)(gate * Hh + colbase + 2 * cg);
    const float* hp = hprevT + 8 * bg;
    const int kend = (ks + 1) * 512;

#pragma unroll 4
    for (int k = ks * 512; k < kend; k++) {
        float2 wv = *(const float2*)(wp + (size_t)k * H3);
        const float* hb = hp + (size_t)k * 32;
        ulonglong2 hl0 = *(const ulonglong2*)(hb);
        ulonglong2 hl1 = *(const ulonglong2*)(hb + 4);
        unsigned long long w0 = pack2(wv.x);
        unsigned long long w1 = pack2(wv.y);
        acc[0][0] = fma2(w0, hl0.x, acc[0][0]);
        acc[0][1] = fma2(w0, hl0.y, acc[0][1]);
        acc[0][2] = fma2(w0, hl1.x, acc[0][2]);
        acc[0][3] = fma2(w0, hl1.y, acc[0][3]);
        acc[1][0] = fma2(w1, hl0.x, acc[1][0]);
        acc[1][1] = fma2(w1, hl0.y, acc[1][1]);
        acc[1][2] = fma2(w1, hl1.x, acc[1][2]);
        acc[1][3] = fma2(w1, hl1.y, acc[1][3]);
    }

#pragma unroll
    for (int i = 0; i < 2; i++)
#pragma unroll
        for (int j = 0; j < 4; j++)
            sred[w][2 * cg + i][4 * bg + j] = ull2f2(acc[i][j]);
    __syncthreads();

    if (tid < 256) {
        const int col = tid >> 4;         // 0..15
        const int bp  = tid & 15;         // bpair 0..15
        const int colg = colbase + col;

        float2 gr = {0.f, 0.f}, gz = {0.f, 0.f}, gn = {0.f, 0.f};
#pragma unroll
        for (int s = 0; s < 4; s++) {
            float2 a = sred[s][col][bp];      gr.x += a.x; gr.y += a.y;
            float2 b = sred[4 + s][col][bp];  gz.x += b.x; gz.y += b.y;
            float2 c = sred[8 + s][col][bp];  gn.x += c.x; gn.y += c.y;
        }
        float br = bhh[colg], bz = bhh[Hh + colg], bn = bhh[2 * Hh + colg];

        float2 ir = *(const float2*)(gi_t + (size_t)colg * 32 + 2 * bp);
        float2 iz = *(const float2*)(gi_t + (size_t)(Hh + colg) * 32 + 2 * bp);
        float2 in = *(const float2*)(gi_t + (size_t)(2 * Hh + colg) * 32 + 2 * bp);
        float2 hv = *(const float2*)(hprevT + (size_t)colg * 32 + 2 * bp);

        float rx = sigm(ir.x + gr.x + br);
        float ry = sigm(ir.y + gr.y + br);
        float zx = sigm(iz.x + gz.x + bz);
        float zy = sigm(iz.y + gz.y + bz);
        float nx = tanhf(in.x + rx * (gn.x + bn));
        float ny = tanhf(in.y + ry * (gn.y + bn));
        float2 hn;
        hn.x = (1.f - zx) * nx + zx * hv.x;
        hn.y = (1.f - zy) * ny + zy * hv.y;
        *(float2*)(hnewT + (size_t)colg * 32 + 2 * bp) = hn;
    }
}

// ---------------- head ------------------------------------------------------------
__global__ __launch_bounds__(256)
void head_kernel(const float* __restrict__ S, const float* __restrict__ Wp,
                 const float* __restrict__ bp, const int* __restrict__ label,
                 float* __restrict__ out)
{
    int w    = blockIdx.x * 8 + (threadIdx.x >> 5);
    int lane = threadIdx.x & 31;
    int bt = w / 3, j = w % 3;
    int t = bt >> 5, b = bt & 31;       // S row = t*32 + b
    int lab = label[b];
    const float* sp = S  + (size_t)bt * Pp;
    const float* wp = Wp + (size_t)(j * 8 + lab) * Pp;
    float sum = 0.f;
    for (int d = lane; d < Pp; d += 32)
        sum = fmaf(sp[d], wp[d], sum);
#pragma unroll
    for (int o = 16; o > 0; o >>= 1) sum += __shfl_xor_sync(0xffffffffu, sum, o);
    if (lane == 0)
        out[(size_t)b * Tt * 3 + t * 3 + j] = sum + bp[j * 8 + lab];
}

__global__ void copy_hlast(const float* __restrict__ srcT, float* __restrict__ dst)
{
    int i = blockIdx.x * 256 + threadIdx.x;      // i = c*32 + b
    if (i < Bb * Hh) {
        int c = i >> 5, b = i & 31;
        dst[(size_t)b * Hh + c] = srcT[i];
    }
}

// ---------------- launch ----------------------------------------------------------
extern "C" void kernel_launch(void* const* d_in, const int* in_sizes, int n_in,
                              void* d_out, int out_size)
{
    (void)in_sizes; (void)n_in; (void)out_size;
    const float* x     = (const float*)d_in[0];
    const int*   label = (const int*)  d_in[1];
    const float* h0    = (const float*)d_in[2];
    const float* W1  = (const float*)d_in[3];  const float* b1  = (const float*)d_in[4];
    const float* W2  = (const float*)d_in[5];  const float* b2  = (const float*)d_in[6];
    const float* Wih = (const float*)d_in[7];  const float* bih = (const float*)d_in[8];
    const float* Whh = (const float*)d_in[9];  const float* bhh = (const float*)d_in[10];
    const float* W3  = (const float*)d_in[11]; const float* b3  = (const float*)d_in[12];
    const float* Wp  = (const float*)d_in[13]; const float* bp  = (const float*)d_in[14];
    float* out = (float*)d_out;

    float *A1, *A2, *GI, *HS, *S, *WT, *h0T;
    cudaGetSymbolAddress((void**)&A1,  g_A1);
    cudaGetSymbolAddress((void**)&A2,  g_A2);
    cudaGetSymbolAddress((void**)&GI,  g_GI);
    cudaGetSymbolAddress((void**)&HS,  g_HS);
    cudaGetSymbolAddress((void**)&S,   g_S);
    cudaGetSymbolAddress((void**)&WT,  g_WT);
    cudaGetSymbolAddress((void**)&h0T, g_h0T);

    // one-time reshapes
    transpose_whh<<<dim3(H3 / 32, Hh / 32), dim3(32, 8)>>>(Whh, WT);
    transpose_h0<<<(Hh * Bb + 255) / 256, 256>>>(h0, h0T);

    // MLP front-end
    sgemm_tn<<<dim3(1024 / BN, MT / BM), 256>>>(x,  W1, b1, A1, MT, 1024, Dd, 1, 0, 0);
    sgemm_tn<<<dim3(Hh   / BN, MT / BM), 256>>>(A1, W2, b2, A2, MT, Hh, 1024, 1, 0, 0);
    // gi written as (T, 3H, B)
    sgemm_tn<<<dim3(H3   / BN, MT / BM), 256>>>(A2, Wih, bih, GI, MT, H3, Hh, 0, 0, 2);

    // GRU scan
    for (int t = 0; t < Tt; t++) {
        const float* hp = (t == 0) ? h0T : (HS + (size_t)(t - 1) * Hh * Bb);
        gru_step<<<Hh / 16, 384>>>(GI + (size_t)t * H3 * Bb, hp, WT, bhh,
                                   HS + (size_t)t * Hh * Bb);
    }

    // out_s = relu(HS @ W3^T + b3); HS is (T, K, B) -> aMode 1, rows r = t*32+b
    sgemm_tn<<<dim3(Pp / BN, MT / BM), 256>>>(HS, W3, b3, S, MT, Pp, Hh, 1, 1, 0);

    head_kernel<<<6144, 256>>>(S, Wp, bp, label, out);
    copy_hlast<<<(Bb * Hh + 255) / 256, 256>>>(HS + (size_t)(Tt - 1) * Hh * Bb,
                                               out + Bb * Tt * 3);
}

// round 3
// speedup vs baseline: 2.0679x; 2.0679x over previous
#include <cuda_runtime.h>
#include <math.h>
#include <stdint.h>

#define Bb 32
#define Tt 512
#define Dd 512
#define Hh 2048
#define H3 6144
#define Pp 1024
#define MT (Bb*Tt)   // 16384
#define PF 8         // prefetch depth in gru mainloop

// ---------------- scratch (device globals; padded for prefetch overrun) -----------
__device__ float g_A1[(size_t)MT * 1024];            //  64 MB relu(x@W1^T+b1)
__device__ float g_A2[(size_t)MT * Hh];              // 128 MB relu(.@W2^T+b2)
__device__ float g_GI[(size_t)MT * H3];              // 384 MB gi, layout (T, 3H, B)
__device__ float g_HS[(size_t)Tt * Hh * Bb + PF*32]; // 128 MB h history (T, H, B)
__device__ float g_S [(size_t)MT * Pp];              //  64 MB relu(h@W3^T+b3)
__device__ float g_WT[(size_t)(Hh + PF) * H3];       //  50 MB W_hh^T : (K, 3H)
__device__ float g_h0T[(Hh + PF) * Bb];              // h0 transposed (H, B)

// ---------------- f32x2 helpers ----------------------------------------------------
__device__ __forceinline__ unsigned long long fma2(unsigned long long a,
                                                   unsigned long long b,
                                                   unsigned long long c) {
    unsigned long long d;
    asm("fma.rn.f32x2 %0, %1, %2, %3;" : "=l"(d) : "l"(a), "l"(b), "l"(c));
    return d;
}
__device__ __forceinline__ unsigned long long pack2(float x) {
    unsigned long long d;
    asm("mov.b64 %0, {%1, %1};" : "=l"(d) : "f"(x));
    return d;
}
__device__ __forceinline__ float2 ull2f2(unsigned long long v) {
    float2 f;
    asm("mov.b64 {%0, %1}, %2;" : "=f"(f.x), "=f"(f.y) : "l"(v));
    return f;
}
__device__ __forceinline__ float sigm(float x) { return 1.f / (1.f + expf(-x)); }

// ---------------- generic TN SGEMM (FMA2 core) -------------------------------------
// C = act(A @ B^T + bias). aMode: 0 = A row-major (M,K);
//   1 = A stored (T,K,B): A[r][k] = A[(r>>5)*K*32 + k*32 + (r&31)], r = t*32+b
// outMode: 0 = C[r][n];  2 = C stored (T,N,B): addr = t*N*32 + n*32 + b, r = b*T+t
#define BM 128
#define BN 128
#define BK 8
#define TM 8
#define TN 8

__global__ __launch_bounds__(256)
void sgemm_tn(const float* __restrict__ A, const float* __restrict__ B,
              const float* __restrict__ bias, float* __restrict__ C,
              int M, int N, int K, int doRelu, int aMode, int outMode)
{
    __shared__ float As[BK][BM];
    __shared__ float Bs[BK][BN];
    const int tid = threadIdx.x;
    const int tx  = tid & 15;
    const int ty  = tid >> 4;
    const int lr  = tid >> 1;
    const int lk  = (tid & 1) * 4;

    const float* Bp = B + (size_t)(blockIdx.x * BN + lr) * K + lk;
    const int rowg = blockIdx.y * BM + lr;
    const float* Ap0 = A + (size_t)rowg * K + lk;
    const float* Ap1 = A + (size_t)(rowg >> 5) * K * 32 + (rowg & 31);

    unsigned long long acc2[TM][TN/2];
#pragma unroll
    for (int i = 0; i < TM; i++)
#pragma unroll
        for (int j = 0; j < TN/2; j++) acc2[i][j] = 0ull;

    for (int k0 = 0; k0 < K; k0 += BK) {
        if (aMode == 0) {
            float4 av = *(const float4*)(Ap0 + k0);
            As[lk + 0][lr] = av.x; As[lk + 1][lr] = av.y;
            As[lk + 2][lr] = av.z; As[lk + 3][lr] = av.w;
        } else {
#pragma unroll
            for (int q = 0; q < 4; q++)
                As[lk + q][lr] = Ap1[(size_t)(k0 + lk + q) * 32];
        }
        float4 bv = *(const float4*)(Bp + k0);
        Bs[lk + 0][lr] = bv.x; Bs[lk + 1][lr] = bv.y;
        Bs[lk + 2][lr] = bv.z; Bs[lk + 3][lr] = bv.w;
        __syncthreads();
#pragma unroll
        for (int k = 0; k < BK; k++) {
            float4 a0 = *(const float4*)&As[k][ty * TM];
            float4 a1 = *(const float4*)&As[k][ty * TM + 4];
            ulonglong2 bq0 = *(const ulonglong2*)&Bs[k][tx * TN];
            ulonglong2 bq1 = *(const ulonglong2*)&Bs[k][tx * TN + 4];
            float ar[TM] = {a0.x, a0.y, a0.z, a0.w, a1.x, a1.y, a1.z, a1.w};
#pragma unroll
            for (int i = 0; i < TM; i++) {
                unsigned long long ap = pack2(ar[i]);
                acc2[i][0] = fma2(ap, bq0.x, acc2[i][0]);
                acc2[i][1] = fma2(ap, bq0.y, acc2[i][1]);
                acc2[i][2] = fma2(ap, bq1.x, acc2[i][2]);
                acc2[i][3] = fma2(ap, bq1.y, acc2[i][3]);
            }
        }
        __syncthreads();
    }

#pragma unroll
    for (int i = 0; i < TM; i++) {
        int r = blockIdx.y * BM + ty * TM + i;
        int colb = blockIdx.x * BN + tx * TN;
        float v[TN];
#pragma unroll
        for (int j = 0; j < TN/2; j++) {
            float2 f = ull2f2(acc2[i][j]);
            v[2*j] = f.x; v[2*j+1] = f.y;
        }
#pragma unroll
        for (int j = 0; j < TN; j++) {
            v[j] += bias[colb + j];
            if (doRelu) v[j] = fmaxf(v[j], 0.f);
        }
        if (outMode == 0) {
            float* Cp = C + (size_t)r * N + colb;
            *(float4*)(Cp)     = make_float4(v[0], v[1], v[2], v[3]);
            *(float4*)(Cp + 4) = make_float4(v[4], v[5], v[6], v[7]);
        } else {  // r = b*T + t  ->  (t, n, b)
            int t = r & (Tt - 1), b = r >> 9;
            float* Cp = C + (size_t)t * N * 32 + b;
#pragma unroll
            for (int j = 0; j < TN; j++)
                Cp[(size_t)(colb + j) * 32] = v[j];
        }
    }
}

// ---------------- one-time transposes ----------------------------------------------
__global__ void transpose_whh(const float* __restrict__ Whh, float* __restrict__ WT)
{
    __shared__ float tile[32][33];
    int c0 = blockIdx.x * 32, k0 = blockIdx.y * 32;
    int x = threadIdx.x, y0 = threadIdx.y;           // block 32 x 8
#pragma unroll
    for (int y = y0; y < 32; y += 8)
        tile[y][x] = Whh[(size_t)(c0 + y) * Hh + k0 + x];
    __syncthreads();
#pragma unroll
    for (int y = y0; y < 32; y += 8)
        WT[(size_t)(k0 + y) * H3 + c0 + x] = tile[x][y];
}

__global__ void transpose_h0(const float* __restrict__ h0, float* __restrict__ h0T)
{
    int i = blockIdx.x * 256 + threadIdx.x;
    if (i < Hh * Bb) {
        int c = i >> 5, b = i & 31;
        h0T[i] = h0[(size_t)b * Hh + c];
    }
}

// ---------------- GRU step: FMA2 register-tiled, software-pipelined ----------------
// grid = 128 blocks (16 hcols each), block = 384 threads = 12 warps =
// (gate in [0,3)) x (ksplit in [0,4), 512 k each).
// Lane: cg = lane>>2 (8 groups x 2 cols), bg = lane&3 (4 groups x 8 batches).
__global__ __launch_bounds__(384)
void gru_step(const float* __restrict__ gi_t,    // (3H, B) slice for this t
              const float* __restrict__ hprevT,  // (H, B)
              const float* __restrict__ WT,      // (K, 3H)
              const float* __restrict__ bhh,
              float* __restrict__ hnewT)         // (H, B)
{
    __shared__ float2 sred[12][16][16];  // [warp][colLocal][bpair]  24 KB

    const int tid  = threadIdx.x;
    const int w    = tid >> 5;
    const int lane = tid & 31;
    const int gate = w >> 2;
    const int ks   = w & 3;
    const int cg   = lane >> 2;
    const int bg   = lane & 3;
    const int colbase = blockIdx.x * 16;

    unsigned long long acc[2][4];
#pragma unroll
    for (int i = 0; i < 2; i++)
#pragma unroll
        for (int j = 0; j < 4; j++) acc[i][j] = 0ull;

    const float* wp = WT + (size_t)(gate * Hh + colbase + 2 * cg);
    const float* hp = hprevT + 8 * bg;
    const int k0 = ks * 512;

    // prefetch ring, depth PF
    float2     wbuf[PF];
    ulonglong2 hbuf0[PF], hbuf1[PF];
#pragma unroll
    for (int p = 0; p < PF; p++) {
        wbuf[p]  = *(const float2*)    (wp + (size_t)(k0 + p) * H3);
        hbuf0[p] = *(const ulonglong2*)(hp + (size_t)(k0 + p) * 32);
        hbuf1[p] = *(const ulonglong2*)(hp + (size_t)(k0 + p) * 32 + 4);
    }

    for (int kb = k0; kb < k0 + 512; kb += PF) {
#pragma unroll
        for (int u = 0; u < PF; u++) {
            float2     wv  = wbuf[u];
            ulonglong2 hl0 = hbuf0[u];
            ulonglong2 hl1 = hbuf1[u];
            // prefetch iteration kb+PF+u (arrays padded: overrun is in-bounds)
            const int kn = kb + PF + u;
            wbuf[u]  = *(const float2*)    (wp + (size_t)kn * H3);
            hbuf0[u] = *(const ulonglong2*)(hp + (size_t)kn * 32);
            hbuf1[u] = *(const ulonglong2*)(hp + (size_t)kn * 32 + 4);

            unsigned long long w0 = pack2(wv.x);
            unsigned long long w1 = pack2(wv.y);
            acc[0][0] = fma2(w0, hl0.x, acc[0][0]);
            acc[0][1] = fma2(w0, hl0.y, acc[0][1]);
            acc[0][2] = fma2(w0, hl1.x, acc[0][2]);
            acc[0][3] = fma2(w0, hl1.y, acc[0][3]);
            acc[1][0] = fma2(w1, hl0.x, acc[1][0]);
            acc[1][1] = fma2(w1, hl0.y, acc[1][1]);
            acc[1][2] = fma2(w1, hl1.x, acc[1][2]);
            acc[1][3] = fma2(w1, hl1.y, acc[1][3]);
        }
    }

#pragma unroll
    for (int i = 0; i < 2; i++)
#pragma unroll
        for (int j = 0; j < 4; j++)
            sred[w][2 * cg + i][4 * bg + j] = ull2f2(acc[i][j]);
    __syncthreads();

    if (tid < 256) {
        const int col = tid >> 4;         // 0..15
        const int bp  = tid & 15;         // bpair 0..15
        const int colg = colbase + col;

        float2 gr = {0.f, 0.f}, gz = {0.f, 0.f}, gn = {0.f, 0.f};
#pragma unroll
        for (int s = 0; s < 4; s++) {
            float2 a = sred[s][col][bp];      gr.x += a.x; gr.y += a.y;
            float2 b = sred[4 + s][col][bp];  gz.x += b.x; gz.y += b.y;
            float2 c = sred[8 + s][col][bp];  gn.x += c.x; gn.y += c.y;
        }
        float br = bhh[colg], bz = bhh[Hh + colg], bn = bhh[2 * Hh + colg];

        float2 ir = *(const float2*)(gi_t + (size_t)colg * 32 + 2 * bp);
        float2 iz = *(const float2*)(gi_t + (size_t)(Hh + colg) * 32 + 2 * bp);
        float2 in = *(const float2*)(gi_t + (size_t)(2 * Hh + colg) * 32 + 2 * bp);
        float2 hv = *(const float2*)(hprevT + (size_t)colg * 32 + 2 * bp);

        float rx = sigm(ir.x + gr.x + br);
        float ry = sigm(ir.y + gr.y + br);
        float zx = sigm(iz.x + gz.x + bz);
        float zy = sigm(iz.y + gz.y + bz);
        float nx = tanhf(in.x + rx * (gn.x + bn));
        float ny = tanhf(in.y + ry * (gn.y + bn));
        float2 hn;
        hn.x = (1.f - zx) * nx + zx * hv.x;
        hn.y = (1.f - zy) * ny + zy * hv.y;
        *(float2*)(hnewT + (size_t)colg * 32 + 2 * bp) = hn;
    }
}

// ---------------- head --------------------------------------------------------------
__global__ __launch_bounds__(256)
void head_kernel(const float* __restrict__ S, const float* __restrict__ Wp,
                 const float* __restrict__ bp, const int* __restrict__ label,
                 float* __restrict__ out)
{
    int w    = blockIdx.x * 8 + (threadIdx.x >> 5);
    int lane = threadIdx.x & 31;
    int bt = w / 3, j = w % 3;
    int t = bt >> 5, b = bt & 31;       // S row = t*32 + b
    int lab = label[b];
    const float* sp = S  + (size_t)bt * Pp;
    const float* wp = Wp + (size_t)(j * 8 + lab) * Pp;
    float sum = 0.f;
    for (int d = lane; d < Pp; d += 32)
        sum = fmaf(sp[d], wp[d], sum);
#pragma unroll
    for (int o = 16; o > 0; o >>= 1) sum += __shfl_xor_sync(0xffffffffu, sum, o);
    if (lane == 0)
        out[(size_t)b * Tt * 3 + t * 3 + j] = sum + bp[j * 8 + lab];
}

__global__ void copy_hlast(const float* __restrict__ srcT, float* __restrict__ dst)
{
    int i = blockIdx.x * 256 + threadIdx.x;      // i = c*32 + b
    if (i < Bb * Hh) {
        int c = i >> 5, b = i & 31;
        dst[(size_t)b * Hh + c] = srcT[i];
    }
}

// ---------------- launch ------------------------------------------------------------
extern "C" void kernel_launch(void* const* d_in, const int* in_sizes, int n_in,
                              void* d_out, int out_size)
{
    (void)in_sizes; (void)n_in; (void)out_size;
    const float* x     = (const float*)d_in[0];
    const int*   label = (const int*)  d_in[1];
    const float* h0    = (const float*)d_in[2];
    const float* W1  = (const float*)d_in[3];  const float* b1  = (const float*)d_in[4];
    const float* W2  = (const float*)d_in[5];  const float* b2  = (const float*)d_in[6];
    const float* Wih = (const float*)d_in[7];  const float* bih = (const float*)d_in[8];
    const float* Whh = (const float*)d_in[9];  const float* bhh = (const float*)d_in[10];
    const float* W3  = (const float*)d_in[11]; const float* b3  = (const float*)d_in[12];
    const float* Wp  = (const float*)d_in[13]; const float* bp  = (const float*)d_in[14];
    float* out = (float*)d_out;

    float *A1, *A2, *GI, *HS, *S, *WT, *h0T;
    cudaGetSymbolAddress((void**)&A1,  g_A1);
    cudaGetSymbolAddress((void**)&A2,  g_A2);
    cudaGetSymbolAddress((void**)&GI,  g_GI);
    cudaGetSymbolAddress((void**)&HS,  g_HS);
    cudaGetSymbolAddress((void**)&S,   g_S);
    cudaGetSymbolAddress((void**)&WT,  g_WT);
    cudaGetSymbolAddress((void**)&h0T, g_h0T);

    // one-time reshapes
    transpose_whh<<<dim3(H3 / 32, Hh / 32), dim3(32, 8)>>>(Whh, WT);
    transpose_h0<<<(Hh * Bb + 255) / 256, 256>>>(h0, h0T);

    // MLP front-end
    sgemm_tn<<<dim3(1024 / BN, MT / BM), 256>>>(x,  W1, b1, A1, MT, 1024, Dd, 1, 0, 0);
    sgemm_tn<<<dim3(Hh   / BN, MT / BM), 256>>>(A1, W2, b2, A2, MT, Hh, 1024, 1, 0, 0);
    // gi written as (T, 3H, B)
    sgemm_tn<<<dim3(H3   / BN, MT / BM), 256>>>(A2, Wih, bih, GI, MT, H3, Hh, 0, 0, 2);

    // GRU scan
    for (int t = 0; t < Tt; t++) {
        const float* hp = (t == 0) ? h0T : (HS + (size_t)(t - 1) * Hh * Bb);
        gru_step<<<Hh / 16, 384>>>(GI + (size_t)t * H3 * Bb, hp, WT, bhh,
                                   HS + (size_t)t * Hh * Bb);
    }

    // out_s = relu(HS @ W3^T + b3); HS is (T,K,B) -> aMode 1, rows r = t*32+b
    sgemm_tn<<<dim3(Pp / BN, MT / BM), 256>>>(HS, W3, b3, S, MT, Pp, Hh, 1, 1, 0);

    head_kernel<<<6144, 256>>>(S, Wp, bp, label, out);
    copy_hlast<<<(Bb * Hh + 255) / 256, 256>>>(HS + (size_t)(Tt - 1) * Hh * Bb,
                                               out + Bb * Tt * 3);
}

// round 4
// speedup vs baseline: 2.2999x; 1.1122x over previous
#include <cuda_runtime.h>
#include <math.h>
#include <stdint.h>

#define Bb 32
#define Tt 512
#define Dd 512
#define Hh 2048
#define H3 6144
#define Pp 1024
#define MT (Bb*Tt)   // 16384
#define PF 8         // prefetch depth in scan mainloop
#define GRID_SCAN 128

// ---------------- scratch (device globals; padded for prefetch overrun) -----------
__device__ float g_A1[(size_t)MT * 1024];
__device__ float g_A2[(size_t)MT * Hh];
__device__ float g_GI[(size_t)MT * H3];              // gi, layout (T, 3H, B)
__device__ float g_HS[(size_t)Tt * Hh * Bb + PF*32]; // h history (T, H, B)
__device__ float g_S [(size_t)MT * Pp];
__device__ float g_WT[(size_t)(Hh + PF) * H3];       // W_hh^T : (K, 3H)
__device__ float g_h0T[(Hh + PF) * Bb];              // h0 transposed (H, B)
__device__ unsigned g_bar_cnt;

// ---------------- f32x2 helpers ----------------------------------------------------
__device__ __forceinline__ unsigned long long fma2(unsigned long long a,
                                                   unsigned long long b,
                                                   unsigned long long c) {
    unsigned long long d;
    asm("fma.rn.f32x2 %0, %1, %2, %3;" : "=l"(d) : "l"(a), "l"(b), "l"(c));
    return d;
}
__device__ __forceinline__ unsigned long long pack2(float x) {
    unsigned long long d;
    asm("mov.b64 %0, {%1, %1};" : "=l"(d) : "f"(x));
    return d;
}
__device__ __forceinline__ float2 ull2f2(unsigned long long v) {
    float2 f;
    asm("mov.b64 {%0, %1}, %2;" : "=f"(f.x), "=f"(f.y) : "l"(v));
    return f;
}
__device__ __forceinline__ float sigm(float x) { return 1.f / (1.f + expf(-x)); }

// ---------------- generic TN SGEMM (FMA2 core, double-buffered) --------------------
// C = act(A @ B^T + bias). aMode: 0 = A row-major (M,K);
//   1 = A stored (T,K,B): A[r][k] = A[(r>>5)*K*32 + k*32 + (r&31)], r = t*32+b
// outMode: 0 = C[r][n];  2 = C stored (T,N,B): addr = t*N*32 + n*32 + b, r = b*T+t
#define BM 128
#define BN 128
#define BK 8
#define TM 8
#define TN 8

__global__ __launch_bounds__(256)
void sgemm_tn(const float* __restrict__ A, const float* __restrict__ B,
              const float* __restrict__ bias, float* __restrict__ C,
              int M, int N, int K, int doRelu, int aMode, int outMode)
{
    __shared__ float As[2][BK][BM];
    __shared__ float Bs[2][BK][BN];
    const int tid = threadIdx.x;
    const int tx  = tid & 15;
    const int ty  = tid >> 4;
    const int lr  = tid >> 1;
    const int lk  = (tid & 1) * 4;

    const float* Bp = B + (size_t)(blockIdx.x * BN + lr) * K + lk;
    const int rowg = blockIdx.y * BM + lr;
    const float* Ap0 = A + (size_t)rowg * K + lk;
    const float* Ap1 = A + (size_t)(rowg >> 5) * K * 32 + (rowg & 31);

    unsigned long long acc2[TM][TN/2];
#pragma unroll
    for (int i = 0; i < TM; i++)
#pragma unroll
        for (int j = 0; j < TN/2; j++) acc2[i][j] = 0ull;

    float rA[4]; float4 rB;
    // prologue: load slab 0
    if (aMode == 0) {
        float4 av = *(const float4*)(Ap0);
        rA[0] = av.x; rA[1] = av.y; rA[2] = av.z; rA[3] = av.w;
    } else {
#pragma unroll
        for (int q = 0; q < 4; q++) rA[q] = Ap1[(size_t)(lk + q) * 32];
    }
    rB = *(const float4*)(Bp);
    int buf = 0;
#pragma unroll
    for (int q = 0; q < 4; q++) As[buf][lk + q][lr] = rA[q];
    Bs[buf][lk + 0][lr] = rB.x; Bs[buf][lk + 1][lr] = rB.y;
    Bs[buf][lk + 2][lr] = rB.z; Bs[buf][lk + 3][lr] = rB.w;
    __syncthreads();

    for (int k0 = 0; k0 < K; k0 += BK) {
        const bool more = (k0 + BK) < K;
        if (more) {  // prefetch next slab to regs (overlaps compute)
            if (aMode == 0) {
                float4 av = *(const float4*)(Ap0 + k0 + BK);
                rA[0] = av.x; rA[1] = av.y; rA[2] = av.z; rA[3] = av.w;
            } else {
#pragma unroll
                for (int q = 0; q < 4; q++)
                    rA[q] = Ap1[(size_t)(k0 + BK + lk + q) * 32];
            }
            rB = *(const float4*)(Bp + k0 + BK);
        }
#pragma unroll
        for (int k = 0; k < BK; k++) {
            float4 a0 = *(const float4*)&As[buf][k][ty * TM];
            float4 a1 = *(const float4*)&As[buf][k][ty * TM + 4];
            ulonglong2 bq0 = *(const ulonglong2*)&Bs[buf][k][tx * TN];
            ulonglong2 bq1 = *(const ulonglong2*)&Bs[buf][k][tx * TN + 4];
            float ar[TM] = {a0.x, a0.y, a0.z, a0.w, a1.x, a1.y, a1.z, a1.w};
#pragma unroll
            for (int i = 0; i < TM; i++) {
                unsigned long long ap = pack2(ar[i]);
                acc2[i][0] = fma2(ap, bq0.x, acc2[i][0]);
                acc2[i][1] = fma2(ap, bq0.y, acc2[i][1]);
                acc2[i][2] = fma2(ap, bq1.x, acc2[i][2]);
                acc2[i][3] = fma2(ap, bq1.y, acc2[i][3]);
            }
        }
        if (more) {
            int nb = buf ^ 1;
#pragma unroll
            for (int q = 0; q < 4; q++) As[nb][lk + q][lr] = rA[q];
            Bs[nb][lk + 0][lr] = rB.x; Bs[nb][lk + 1][lr] = rB.y;
            Bs[nb][lk + 2][lr] = rB.z; Bs[nb][lk + 3][lr] = rB.w;
            __syncthreads();
            buf = nb;
        }
    }

#pragma unroll
    for (int i = 0; i < TM; i++) {
        int r = blockIdx.y * BM + ty * TM + i;
        int colb = blockIdx.x * BN + tx * TN;
        float v[TN];
#pragma unroll
        for (int j = 0; j < TN/2; j++) {
            float2 f = ull2f2(acc2[i][j]);
            v[2*j] = f.x; v[2*j+1] = f.y;
        }
#pragma unroll
        for (int j = 0; j < TN; j++) {
            v[j] += bias[colb + j];
            if (doRelu) v[j] = fmaxf(v[j], 0.f);
        }
        if (outMode == 0) {
            float* Cp = C + (size_t)r * N + colb;
            *(float4*)(Cp)     = make_float4(v[0], v[1], v[2], v[3]);
            *(float4*)(Cp + 4) = make_float4(v[4], v[5], v[6], v[7]);
        } else {  // r = b*T + t  ->  (t, n, b)
            int t = r & (Tt - 1), b = r >> 9;
            float* Cp = C + (size_t)t * N * 32 + b;
#pragma unroll
            for (int j = 0; j < TN; j++)
                Cp[(size_t)(colb + j) * 32] = v[j];
        }
    }
}

// ---------------- one-time transposes ----------------------------------------------
__global__ void transpose_whh(const float* __restrict__ Whh, float* __restrict__ WT)
{
    __shared__ float tile[32][33];
    int c0 = blockIdx.x * 32, k0 = blockIdx.y * 32;
    int x = threadIdx.x, y0 = threadIdx.y;
#pragma unroll
    for (int y = y0; y < 32; y += 8)
        tile[y][x] = Whh[(size_t)(c0 + y) * Hh + k0 + x];
    __syncthreads();
#pragma unroll
    for (int y = y0; y < 32; y += 8)
        WT[(size_t)(k0 + y) * H3 + c0 + x] = tile[x][y];
}

__global__ void transpose_h0(const float* __restrict__ h0, float* __restrict__ h0T)
{
    int i = blockIdx.x * 256 + threadIdx.x;
    if (i < Hh * Bb) {
        int c = i >> 5, b = i & 31;
        h0T[i] = h0[(size_t)b * Hh + c];
    }
}

__global__ void reset_bar() { g_bar_cnt = 0u; }

// ---------------- persistent GRU scan ----------------------------------------------
// 128 blocks x 384 threads. Block covers 16 h-cols. 12 warps = gate(3) x ksplit(4).
// Lane: cg = lane>>3 (4 colgroups x 4 cols, float4 weight), bg = lane&7
// (8 bgroups x 4 batches = 2 bpairs, one ulonglong2 h load). acc[4][2] f32x2.
__global__ __launch_bounds__(384, 1)
void gru_scan(const float* __restrict__ gi0,    // (T, 3H, B)
              const float* __restrict__ h0T,    // (H, B)
              const float* __restrict__ WT,     // (K, 3H)
              const float* __restrict__ bhh,
              float* __restrict__ HS)           // (T, H, B)
{
    __shared__ float2 sred[12][16][16];  // [warp][colLocal][bpair] 24 KB

    const int tid  = threadIdx.x;
    const int w    = tid >> 5;
    const int lane = tid & 31;
    const int gate = w >> 2;
    const int ks   = w & 3;
    const int cg   = lane >> 3;   // 0..3
    const int bg   = lane & 7;    // 0..7
    const int colbase = blockIdx.x * 16;
    const int k0 = ks * 512;

    const float* wbase = WT + (size_t)k0 * H3 + (gate * Hh + colbase + 4 * cg);
    const unsigned bar_unit = GRID_SCAN;

    // epilogue thread mapping
    const int ecol = tid >> 4;   // 0..15 (valid for tid<256)
    const int ebp  = tid & 15;
    const int colg = colbase + ecol;
    float br = 0.f, bz = 0.f, bn = 0.f;
    if (tid < 256) {
        br = bhh[colg]; bz = bhh[Hh + colg]; bn = bhh[2 * Hh + colg];
    }

    for (int t = 0; t < Tt; t++) {
        const float* hp = (t == 0) ? h0T : (HS + (size_t)(t - 1) * Hh * Bb);
        const float* gi_t = gi0 + (size_t)t * H3 * Bb;

        unsigned long long acc[4][2];
#pragma unroll
        for (int c = 0; c < 4; c++) { acc[c][0] = 0ull; acc[c][1] = 0ull; }

        const float* wpf = wbase;
        const float* hpf = hp + (size_t)k0 * 32 + 4 * bg;

        float4     wbuf[PF];
        ulonglong2 hbuf[PF];
#pragma unroll
        for (int p = 0; p < PF; p++) {
            wbuf[p] = *(const float4*)wpf;
            hbuf[p] = *(const ulonglong2*)hpf;
            wpf += H3; hpf += 32;
        }

        for (int kb = 0; kb < 512; kb += PF) {
#pragma unroll
            for (int u = 0; u < PF; u++) {
                float4     w4 = wbuf[u];
                ulonglong2 hq = hbuf[u];
                wbuf[u] = *(const float4*)wpf;      // padded overrun is in-bounds
                hbuf[u] = *(const ulonglong2*)hpf;
                wpf += H3; hpf += 32;

                unsigned long long p0 = pack2(w4.x);
                unsigned long long p1 = pack2(w4.y);
                unsigned long long p2 = pack2(w4.z);
                unsigned long long p3 = pack2(w4.w);
                acc[0][0] = fma2(p0, hq.x, acc[0][0]);
                acc[0][1] = fma2(p0, hq.y, acc[0][1]);
                acc[1][0] = fma2(p1, hq.x, acc[1][0]);
                acc[1][1] = fma2(p1, hq.y, acc[1][1]);
                acc[2][0] = fma2(p2, hq.x, acc[2][0]);
                acc[2][1] = fma2(p2, hq.y, acc[2][1]);
                acc[3][0] = fma2(p3, hq.x, acc[3][0]);
                acc[3][1] = fma2(p3, hq.y, acc[3][1]);
            }
        }

#pragma unroll
        for (int c = 0; c < 4; c++) {
            sred[w][4 * cg + c][2 * bg + 0] = ull2f2(acc[c][0]);
            sred[w][4 * cg + c][2 * bg + 1] = ull2f2(acc[c][1]);
        }
        __syncthreads();

        if (tid < 256) {
            float2 gr = {0.f, 0.f}, gz = {0.f, 0.f}, gn = {0.f, 0.f};
#pragma unroll
            for (int s = 0; s < 4; s++) {
                float2 a = sred[s][ecol][ebp];      gr.x += a.x; gr.y += a.y;
                float2 b = sred[4 + s][ecol][ebp];  gz.x += b.x; gz.y += b.y;
                float2 c = sred[8 + s][ecol][ebp];  gn.x += c.x; gn.y += c.y;
            }
            float2 ir = *(const float2*)(gi_t + (size_t)colg * 32 + 2 * ebp);
            float2 iz = *(const float2*)(gi_t + (size_t)(Hh + colg) * 32 + 2 * ebp);
            float2 in = *(const float2*)(gi_t + (size_t)(2 * Hh + colg) * 32 + 2 * ebp);
            float2 hv = *(const float2*)(hp + (size_t)colg * 32 + 2 * ebp);

            float rx = sigm(ir.x + gr.x + br);
            float ry = sigm(ir.y + gr.y + br);
            float zx = sigm(iz.x + gz.x + bz);
            float zy = sigm(iz.y + gz.y + bz);
            float nx = tanhf(in.x + rx * (gn.x + bn));
            float ny = tanhf(in.y + ry * (gn.y + bn));
            float2 hn;
            hn.x = (1.f - zx) * nx + zx * hv.x;
            hn.y = (1.f - zy) * ny + zy * hv.y;
            *(float2*)(HS + (size_t)t * Hh * Bb + (size_t)colg * 32 + 2 * ebp) = hn;
        }

        // -------- grid sync --------
        __syncthreads();
        if (tid == 0) {
            __threadfence();                       // publish this block's h writes
            atomicAdd(&g_bar_cnt, 1u);
            const unsigned target = (unsigned)(t + 1) * bar_unit;
            unsigned v;
            do {
                asm volatile("ld.global.acquire.gpu.b32 %0, [%1];"
                             : "=r"(v) : "l"(&g_bar_cnt));
                if (v >= target) break;
                __nanosleep(64);
            } while (true);
        }
        __syncthreads();
    }
}

// ---------------- head --------------------------------------------------------------
__global__ __launch_bounds__(256)
void head_kernel(const float* __restrict__ S, const float* __restrict__ Wp,
                 const float* __restrict__ bp, const int* __restrict__ label,
                 float* __restrict__ out)
{
    int w    = blockIdx.x * 8 + (threadIdx.x >> 5);
    int lane = threadIdx.x & 31;
    int bt = w / 3, j = w % 3;
    int t = bt >> 5, b = bt & 31;       // S row = t*32 + b
    int lab = label[b];
    const float* sp = S  + (size_t)bt * Pp;
    const float* wp = Wp + (size_t)(j * 8 + lab) * Pp;
    float sum = 0.f;
    for (int d = lane; d < Pp; d += 32)
        sum = fmaf(sp[d], wp[d], sum);
#pragma unroll
    for (int o = 16; o > 0; o >>= 1) sum += __shfl_xor_sync(0xffffffffu, sum, o);
    if (lane == 0)
        out[(size_t)b * Tt * 3 + t * 3 + j] = sum + bp[j * 8 + lab];
}

__global__ void copy_hlast(const float* __restrict__ srcT, float* __restrict__ dst)
{
    int i = blockIdx.x * 256 + threadIdx.x;      // i = c*32 + b
    if (i < Bb * Hh) {
        int c = i >> 5, b = i & 31;
        dst[(size_t)b * Hh + c] = srcT[i];
    }
}

// ---------------- launch ------------------------------------------------------------
extern "C" void kernel_launch(void* const* d_in, const int* in_sizes, int n_in,
                              void* d_out, int out_size)
{
    (void)in_sizes; (void)n_in; (void)out_size;
    const float* x     = (const float*)d_in[0];
    const int*   label = (const int*)  d_in[1];
    const float* h0    = (const float*)d_in[2];
    const float* W1  = (const float*)d_in[3];  const float* b1  = (const float*)d_in[4];
    const float* W2  = (const float*)d_in[5];  const float* b2  = (const float*)d_in[6];
    const float* Wih = (const float*)d_in[7];  const float* bih = (const float*)d_in[8];
    const float* Whh = (const float*)d_in[9];  const float* bhh = (const float*)d_in[10];
    const float* W3  = (const float*)d_in[11]; const float* b3  = (const float*)d_in[12];
    const float* Wp  = (const float*)d_in[13]; const float* bp  = (const float*)d_in[14];
    float* out = (float*)d_out;

    float *A1, *A2, *GI, *HS, *S, *WT, *h0T;
    cudaGetSymbolAddress((void**)&A1,  g_A1);
    cudaGetSymbolAddress((void**)&A2,  g_A2);
    cudaGetSymbolAddress((void**)&GI,  g_GI);
    cudaGetSymbolAddress((void**)&HS,  g_HS);
    cudaGetSymbolAddress((void**)&S,   g_S);
    cudaGetSymbolAddress((void**)&WT,  g_WT);
    cudaGetSymbolAddress((void**)&h0T, g_h0T);

    // one-time reshapes + barrier reset
    transpose_whh<<<dim3(H3 / 32, Hh / 32), dim3(32, 8)>>>(Whh, WT);
    transpose_h0<<<(Hh * Bb + 255) / 256, 256>>>(h0, h0T);
    reset_bar<<<1, 1>>>();

    // MLP front-end
    sgemm_tn<<<dim3(1024 / BN, MT / BM), 256>>>(x,  W1, b1, A1, MT, 1024, Dd, 1, 0, 0);
    sgemm_tn<<<dim3(Hh   / BN, MT / BM), 256>>>(A1, W2, b2, A2, MT, Hh, 1024, 1, 0, 0);
    // gi written as (T, 3H, B)
    sgemm_tn<<<dim3(H3   / BN, MT / BM), 256>>>(A2, Wih, bih, GI, MT, H3, Hh, 0, 0, 2);

    // persistent GRU scan (all 512 steps in one launch)
    gru_scan<<<GRID_SCAN, 384>>>(GI, h0T, WT, bhh, HS);

    // out_s = relu(HS @ W3^T + b3); HS is (T,K,B) -> aMode 1, rows r = t*32+b
    sgemm_tn<<<dim3(Pp / BN, MT / BM), 256>>>(HS, W3, b3, S, MT, Pp, Hh, 1, 1, 0);

    head_kernel<<<6144, 256>>>(S, Wp, bp, label, out);
    copy_hlast<<<(Bb * Hh + 255) / 256, 256>>>(HS + (size_t)(Tt - 1) * Hh * Bb,
                                               out + Bb * Tt * 3);
}

// round 7
// speedup vs baseline: 2.3093x; 1.0041x over previous
#include <cuda_runtime.h>
#include <math.h>
#include <stdint.h>

#define Bb 32
#define Tt 512
#define Dd 512
#define Hh 2048
#define H3 6144
#define Pp 1024
#define MT (Bb*Tt)   // 16384
#define PF 8         // prefetch ring depth (weights and h)
#define GRID_SCAN 128

// ---------------- scratch (device globals; padded for prefetch overrun) -----------
__device__ float g_A1[(size_t)MT * 1024];
__device__ float g_A2[(size_t)MT * Hh];
__device__ float g_GI[(size_t)MT * H3];              // gi, layout (T, 3H, B)
__device__ float g_HS[(size_t)Tt * Hh * Bb + PF*32]; // h history (T, H, B)
__device__ float g_S [(size_t)MT * Pp];
__device__ float g_WT[(size_t)(Hh + PF) * H3];       // W_hh^T : (K, 3H)
__device__ float g_h0T[(Hh + PF) * Bb];              // h0 transposed (H, B)
__device__ unsigned g_bar_cnt;

// ---------------- helpers ----------------------------------------------------------
__device__ __forceinline__ unsigned long long fma2(unsigned long long a,
                                                   unsigned long long b,
                                                   unsigned long long c) {
    unsigned long long d;
    asm("fma.rn.f32x2 %0, %1, %2, %3;" : "=l"(d) : "l"(a), "l"(b), "l"(c));
    return d;
}
__device__ __forceinline__ unsigned long long pack2(float x) {
    unsigned long long d;
    asm("mov.b64 %0, {%1, %1};" : "=l"(d) : "f"(x));
    return d;
}
__device__ __forceinline__ float2 ull2f2(unsigned long long v) {
    float2 f;
    asm("mov.b64 {%0, %1}, %2;" : "=f"(f.x), "=f"(f.y) : "l"(v));
    return f;
}
__device__ __forceinline__ unsigned long long mk_evict_last_policy() {
    unsigned long long pol;
    asm("createpolicy.fractional.L2::evict_last.b64 %0, 1.0;" : "=l"(pol));
    return pol;
}
__device__ __forceinline__ float4 ldg_pol(const float* p, unsigned long long pol) {
    float4 v;
    asm("ld.global.nc.L2::cache_hint.v4.f32 {%0,%1,%2,%3}, [%4], %5;"
        : "=f"(v.x), "=f"(v.y), "=f"(v.z), "=f"(v.w) : "l"(p), "l"(pol));
    return v;
}
__device__ __forceinline__ float sigm(float x) { return 1.f / (1.f + expf(-x)); }

// ---------------- generic TN SGEMM (FMA2 core, double-buffered, k-pipelined) -------
// C = act(A @ B^T + bias). aMode: 0 = A row-major (M,K);
//   1 = A stored (T,K,B): A[r][k] = A[(r>>5)*K*32 + k*32 + (r&31)], r = t*32+b
// outMode: 0 = C[r][n];  2 = C stored (T,N,B): addr = t*N*32 + n*32 + b, r = b*T+t
#define BM 128
#define BN 128
#define BK 8
#define TM 8
#define TN 8

__global__ __launch_bounds__(256)
void sgemm_tn(const float* __restrict__ A, const float* __restrict__ B,
              const float* __restrict__ bias, float* __restrict__ C,
              int M, int N, int K, int doRelu, int aMode, int outMode)
{
    __shared__ float As[2][BK][BM];
    __shared__ float Bs[2][BK][BN];
    const int tid = threadIdx.x;
    const int tx  = tid & 15;
    const int ty  = tid >> 4;
    const int lr  = tid >> 1;
    const int lk  = (tid & 1) * 4;

    const float* Bp = B + (size_t)(blockIdx.x * BN + lr) * K + lk;
    const int rowg = blockIdx.y * BM + lr;
    const float* Ap0 = A + (size_t)rowg * K + lk;
    const float* Ap1 = A + (size_t)(rowg >> 5) * K * 32 + (rowg & 31);

    unsigned long long acc2[TM][TN/2];
#pragma unroll
    for (int i = 0; i < TM; i++)
#pragma unroll
        for (int j = 0; j < TN/2; j++) acc2[i][j] = 0ull;

    float rA[4]; float4 rB;
    if (aMode == 0) {
        float4 av = *(const float4*)(Ap0);
        rA[0] = av.x; rA[1] = av.y; rA[2] = av.z; rA[3] = av.w;
    } else {
#pragma unroll
        for (int q = 0; q < 4; q++) rA[q] = Ap1[(size_t)(lk + q) * 32];
    }
    rB = *(const float4*)(Bp);
    int buf = 0;
#pragma unroll
    for (int q = 0; q < 4; q++) As[buf][lk + q][lr] = rA[q];
    Bs[buf][lk + 0][lr] = rB.x; Bs[buf][lk + 1][lr] = rB.y;
    Bs[buf][lk + 2][lr] = rB.z; Bs[buf][lk + 3][lr] = rB.w;
    __syncthreads();

    for (int k0 = 0; k0 < K; k0 += BK) {
        const bool more = (k0 + BK) < K;
        if (more) {  // global prefetch of next slab into registers
            if (aMode == 0) {
                float4 av = *(const float4*)(Ap0 + k0 + BK);
                rA[0] = av.x; rA[1] = av.y; rA[2] = av.z; rA[3] = av.w;
            } else {
#pragma unroll
                for (int q = 0; q < 4; q++)
                    rA[q] = Ap1[(size_t)(k0 + BK + lk + q) * 32];
            }
            rB = *(const float4*)(Bp + k0 + BK);
        }
        // smem-fragment software pipeline: load k+1 while computing k
        float4 ca0 = *(const float4*)&As[buf][0][ty * TM];
        float4 ca1 = *(const float4*)&As[buf][0][ty * TM + 4];
        ulonglong2 cb0 = *(const ulonglong2*)&Bs[buf][0][tx * TN];
        ulonglong2 cb1 = *(const ulonglong2*)&Bs[buf][0][tx * TN + 4];
#pragma unroll
        for (int k = 0; k < BK; k++) {
            const int kn = (k + 1) & (BK - 1);
            float4 na0 = *(const float4*)&As[buf][kn][ty * TM];
            float4 na1 = *(const float4*)&As[buf][kn][ty * TM + 4];
            ulonglong2 nb0 = *(const ulonglong2*)&Bs[buf][kn][tx * TN];
            ulonglong2 nb1 = *(const ulonglong2*)&Bs[buf][kn][tx * TN + 4];
            float ar[TM] = {ca0.x, ca0.y, ca0.z, ca0.w, ca1.x, ca1.y, ca1.z, ca1.w};
#pragma unroll
            for (int i = 0; i < TM; i++) {
                unsigned long long ap = pack2(ar[i]);
                acc2[i][0] = fma2(ap, cb0.x, acc2[i][0]);
                acc2[i][1] = fma2(ap, cb0.y, acc2[i][1]);
                acc2[i][2] = fma2(ap, cb1.x, acc2[i][2]);
                acc2[i][3] = fma2(ap, cb1.y, acc2[i][3]);
            }
            ca0 = na0; ca1 = na1; cb0 = nb0; cb1 = nb1;
        }
        if (more) {
            int nb = buf ^ 1;
#pragma unroll
            for (int q = 0; q < 4; q++) As[nb][lk + q][lr] = rA[q];
            Bs[nb][lk + 0][lr] = rB.x; Bs[nb][lk + 1][lr] = rB.y;
            Bs[nb][lk + 2][lr] = rB.z; Bs[nb][lk + 3][lr] = rB.w;
            __syncthreads();
            buf = nb;
        }
    }

#pragma unroll
    for (int i = 0; i < TM; i++) {
        int r = blockIdx.y * BM + ty * TM + i;
        int colb = blockIdx.x * BN + tx * TN;
        float v[TN];
#pragma unroll
        for (int j = 0; j < TN/2; j++) {
            float2 f = ull2f2(acc2[i][j]);
            v[2*j] = f.x; v[2*j+1] = f.y;
        }
#pragma unroll
        for (int j = 0; j < TN; j++) {
            v[j] += bias[colb + j];
            if (doRelu) v[j] = fmaxf(v[j], 0.f);
        }
        if (outMode == 0) {
            float* Cp = C + (size_t)r * N + colb;
            *(float4*)(Cp)     = make_float4(v[0], v[1], v[2], v[3]);
            *(float4*)(Cp + 4) = make_float4(v[4], v[5], v[6], v[7]);
        } else {  // r = b*T + t  ->  (t, n, b)
            int t = r & (Tt - 1), b = r >> 9;
            float* Cp = C + (size_t)t * N * 32 + b;
#pragma unroll
            for (int j = 0; j < TN; j++)
                Cp[(size_t)(colb + j) * 32] = v[j];
        }
    }
}

// ---------------- one-time transposes ----------------------------------------------
__global__ void transpose_whh(const float* __restrict__ Whh, float* __restrict__ WT)
{
    __shared__ float tile[32][33];
    int c0 = blockIdx.x * 32, k0 = blockIdx.y * 32;
    int x = threadIdx.x, y0 = threadIdx.y;
#pragma unroll
    for (int y = y0; y < 32; y += 8)
        tile[y][x] = Whh[(size_t)(c0 + y) * Hh + k0 + x];
    __syncthreads();
#pragma unroll
    for (int y = y0; y < 32; y += 8)
        WT[(size_t)(k0 + y) * H3 + c0 + x] = tile[x][y];
}

__global__ void transpose_h0(const float* __restrict__ h0, float* __restrict__ h0T)
{
    int i = blockIdx.x * 256 + threadIdx.x;
    if (i < Hh * Bb) {
        int c = i >> 5, b = i & 31;
        h0T[i] = h0[(size_t)b * Hh + c];
    }
}

__global__ void reset_bar() { g_bar_cnt = 0u; }

// ---------------- persistent GRU scan ----------------------------------------------
// 128 blocks x 384 threads. Block = 16 h-cols. 12 warps = gate(3) x ksplit(4).
// Lane: cg = lane>>3 (4 colgroups x 4 cols, float4 weight), bg = lane&7
// (8 bgroups x 4 batches, one ulonglong2 h load). acc[4][2] f32x2.
__global__ __launch_bounds__(384, 1)
void gru_scan(const float* __restrict__ gi0,    // (T, 3H, B)
              const float* __restrict__ h0T,    // (H, B)
              const float* __restrict__ WT,     // (K, 3H)
              const float* __restrict__ bhh,
              float* __restrict__ HS)           // (T, H, B)
{
    __shared__ float2 sred[12][16][16];  // [warp][colLocal][bpair] 24 KB

    const int tid  = threadIdx.x;
    const int w    = tid >> 5;
    const int lane = tid & 31;
    const int gate = w >> 2;
    const int ks   = w & 3;
    const int cg   = lane >> 3;   // 0..3
    const int bg   = lane & 7;    // 0..7
    const int colbase = blockIdx.x * 16;
    const int k0 = ks * 512;

    const unsigned long long pol = mk_evict_last_policy();
    const float* wbase = WT + (size_t)k0 * H3 + (gate * Hh + colbase + 4 * cg);
    const unsigned bar_unit = GRID_SCAN;

    const int ecol = tid >> 4;   // 0..15 (valid for tid<256)
    const int ebp  = tid & 15;
    const int colg = colbase + ecol;
    float br = 0.f, bz = 0.f, bn = 0.f;
    if (tid < 256) {
        br = bhh[colg]; bz = bhh[Hh + colg]; bn = bhh[2 * Hh + colg];
    }

    // prime weight ring for t = 0 (rows k0 .. k0+PF-1)
    float4 wbuf[PF];
    {
        const float* p = wbase;
#pragma unroll
        for (int q = 0; q < PF; q++) { wbuf[q] = ldg_pol(p, pol); p += H3; }
    }

    for (int t = 0; t < Tt; t++) {
        const float* hp = (t == 0) ? h0T : (HS + (size_t)(t - 1) * Hh * Bb);
        const float* gi_t = gi0 + (size_t)t * H3 * Bb;

        unsigned long long acc[4][2];
#pragma unroll
        for (int c = 0; c < 4; c++) { acc[c][0] = 0ull; acc[c][1] = 0ull; }

        const float* hbase = hp + (size_t)k0 * 32 + 4 * bg;
        ulonglong2 hbuf[PF];
        {
            const float* p = hbase;
#pragma unroll
            for (int q = 0; q < PF; q++) { hbuf[q] = *(const ulonglong2*)p; p += 32; }
        }
        const float* wpf = wbase + (size_t)PF * H3;  // refill row k0+PF
        const float* hpf = hbase + (size_t)PF * 32;

        for (int kb = 0; kb < 512; kb += PF) {
#pragma unroll
            for (int u = 0; u < PF; u++) {
                float4     w4 = wbuf[u];
                ulonglong2 hq = hbuf[u];
                wbuf[u] = ldg_pol(wpf, pol);         wpf += H3;   // padded overrun OK
                hbuf[u] = *(const ulonglong2*)hpf;   hpf += 32;

                unsigned long long p0 = pack2(w4.x);
                unsigned long long p1 = pack2(w4.y);
                unsigned long long p2 = pack2(w4.z);
                unsigned long long p3 = pack2(w4.w);
                acc[0][0] = fma2(p0, hq.x, acc[0][0]);
                acc[0][1] = fma2(p0, hq.y, acc[0][1]);
                acc[1][0] = fma2(p1, hq.x, acc[1][0]);
                acc[1][1] = fma2(p1, hq.y, acc[1][1]);
                acc[2][0] = fma2(p2, hq.x, acc[2][0]);
                acc[2][1] = fma2(p2, hq.y, acc[2][1]);
                acc[3][0] = fma2(p3, hq.x, acc[3][0]);
                acc[3][1] = fma2(p3, hq.y, acc[3][1]);
            }
        }

        // re-prime weight ring for next step (overlaps epilogue + barrier wait)
        {
            const float* p = wbase;
#pragma unroll
            for (int q = 0; q < PF; q++) { wbuf[q] = ldg_pol(p, pol); p += H3; }
        }

#pragma unroll
        for (int c = 0; c < 4; c++) {
            sred[w][4 * cg + c][2 * bg + 0] = ull2f2(acc[c][0]);
            sred[w][4 * cg + c][2 * bg + 1] = ull2f2(acc[c][1]);
        }
        __syncthreads();

        if (tid < 256) {
            float2 gr = {0.f, 0.f}, gz = {0.f, 0.f}, gn = {0.f, 0.f};
#pragma unroll
            for (int s = 0; s < 4; s++) {
                float2 a = sred[s][ecol][ebp];      gr.x += a.x; gr.y += a.y;
                float2 b = sred[4 + s][ecol][ebp];  gz.x += b.x; gz.y += b.y;
                float2 c = sred[8 + s][ecol][ebp];  gn.x += c.x; gn.y += c.y;
            }
            float2 ir = *(const float2*)(gi_t + (size_t)colg * 32 + 2 * ebp);
            float2 iz = *(const float2*)(gi_t + (size_t)(Hh + colg) * 32 + 2 * ebp);
            float2 in = *(const float2*)(gi_t + (size_t)(2 * Hh + colg) * 32 + 2 * ebp);
            float2 hv = *(const float2*)(hp + (size_t)colg * 32 + 2 * ebp);

            float rx = sigm(ir.x + gr.x + br);
            float ry = sigm(ir.y + gr.y + br);
            float zx = sigm(iz.x + gz.x + bz);
            float zy = sigm(iz.y + gz.y + bz);
            float nx = tanhf(in.x + rx * (gn.x + bn));
            float ny = tanhf(in.y + ry * (gn.y + bn));
            float2 hn;
            hn.x = (1.f - zx) * nx + zx * hv.x;
            hn.y = (1.f - zy) * ny + zy * hv.y;
            *(float2*)(HS + (size_t)t * Hh * Bb + (size_t)colg * 32 + 2 * ebp) = hn;
        }

        // -------- grid sync --------
        __syncthreads();
        if (tid == 0) {
            __threadfence();
            atomicAdd(&g_bar_cnt, 1u);
            const unsigned target = (unsigned)(t + 1) * bar_unit;
            unsigned v;
            do {
                asm volatile("ld.global.acquire.gpu.b32 %0, [%1];"
                             : "=r"(v) : "l"(&g_bar_cnt));
                if (v >= target) break;
                __nanosleep(64);
            } while (true);
        }
        __syncthreads();
    }
}

// ---------------- head --------------------------------------------------------------
__global__ __launch_bounds__(256)
void head_kernel(const float* __restrict__ S, const float* __restrict__ Wp,
                 const float* __restrict__ bp, const int* __restrict__ label,
                 float* __restrict__ out)
{
    int w    = blockIdx.x * 8 + (threadIdx.x >> 5);
    int lane = threadIdx.x & 31;
    int bt = w / 3, j = w % 3;
    int t = bt >> 5, b = bt & 31;       // S row = t*32 + b
    int lab = label[b];
    const float* sp = S  + (size_t)bt * Pp;
    const float* wp = Wp + (size_t)(j * 8 + lab) * Pp;
    float sum = 0.f;
    for (int d = lane; d < Pp; d += 32)
        sum = fmaf(sp[d], wp[d], sum);
#pragma unroll
    for (int o = 16; o > 0; o >>= 1) sum += __shfl_xor_sync(0xffffffffu, sum, o);
    if (lane == 0)
        out[(size_t)b * Tt * 3 + t * 3 + j] = sum + bp[j * 8 + lab];
}

__global__ void copy_hlast(const float* __restrict__ srcT, float* __restrict__ dst)
{
    int i = blockIdx.x * 256 + threadIdx.x;      // i = c*32 + b
    if (i < Bb * Hh) {
        int c = i >> 5, b = i & 31;
        dst[(size_t)b * Hh + c] = srcT[i];
    }
}

// ---------------- launch ------------------------------------------------------------
extern "C" void kernel_launch(void* const* d_in, const int* in_sizes, int n_in,
                              void* d_out, int out_size)
{
    (void)in_sizes; (void)n_in; (void)out_size;
    const float* x     = (const float*)d_in[0];
    const int*   label = (const int*)  d_in[1];
    const float* h0    = (const float*)d_in[2];
    const float* W1  = (const float*)d_in[3];  const float* b1  = (const float*)d_in[4];
    const float* W2  = (const float*)d_in[5];  const float* b2  = (const float*)d_in[6];
    const float* Wih = (const float*)d_in[7];  const float* bih = (const float*)d_in[8];
    const float* Whh = (const float*)d_in[9];  const float* bhh = (const float*)d_in[10];
    const float* W3  = (const float*)d_in[11]; const float* b3  = (const float*)d_in[12];
    const float* Wp  = (const float*)d_in[13]; const float* bp  = (const float*)d_in[14];
    float* out = (float*)d_out;

    float *A1, *A2, *GI, *HS, *S, *WT, *h0T;
    cudaGetSymbolAddress((void**)&A1,  g_A1);
    cudaGetSymbolAddress((void**)&A2,  g_A2);
    cudaGetSymbolAddress((void**)&GI,  g_GI);
    cudaGetSymbolAddress((void**)&HS,  g_HS);
    cudaGetSymbolAddress((void**)&S,   g_S);
    cudaGetSymbolAddress((void**)&WT,  g_WT);
    cudaGetSymbolAddress((void**)&h0T, g_h0T);

    // one-time reshapes + barrier reset
    transpose_whh<<<dim3(H3 / 32, Hh / 32), dim3(32, 8)>>>(Whh, WT);
    transpose_h0<<<(Hh * Bb + 255) / 256, 256>>>(h0, h0T);
    reset_bar<<<1, 1>>>();

    // MLP front-end
    sgemm_tn<<<dim3(1024 / BN, MT / BM), 256>>>(x,  W1, b1, A1, MT, 1024, Dd, 1, 0, 0);
    sgemm_tn<<<dim3(Hh   / BN, MT / BM), 256>>>(A1, W2, b2, A2, MT, Hh, 1024, 1, 0, 0);
    // gi written as (T, 3H, B)
    sgemm_tn<<<dim3(H3   / BN, MT / BM), 256>>>(A2, Wih, bih, GI, MT, H3, Hh, 0, 0, 2);

    // persistent GRU scan (all 512 steps in one launch)
    gru_scan<<<GRID_SCAN, 384>>>(GI, h0T, WT, bhh, HS);

    // out_s = relu(HS @ W3^T + b3); HS is (T,K,B) -> aMode 1, rows r = t*32+b
    sgemm_tn<<<dim3(Pp / BN, MT / BM), 256>>>(HS, W3, b3, S, MT, Pp, Hh, 1, 1, 0);

    head_kernel<<<6144, 256>>>(S, Wp, bp, label, out);
    copy_hlast<<<(Bb * Hh + 255) / 256, 256>>>(HS + (size_t)(Tt - 1) * Hh * Bb,
                                               out + Bb * Tt * 3);
}